// round 11
// baseline (speedup 1.0000x reference)
#include <cuda_runtime.h>
#include <cuda_fp16.h>
#include <math.h>
#include <stdint.h>

#define Bn   8
#define Tn   128
#define U1n  33
#define Dn   512
#define Vn   4096
#define BTU  (Tn*U1n)          // 4224
#define ROWS (Bn*BTU)          // 33792
#define MTL  (ROWS/128)        // 264 M-tiles
#define NVT  (Vn/128)          // 32 vocab tiles
#define NCTA 148
#define UTOT (MTL*NVT)         // 8448 work units
#define UBASE (UTOT/NCTA)      // 57
#define UREM  (UTOT - UBASE*NCTA) // 12
#define L2E  1.442695040888963f

// smem layout (bytes)
#define SM_A     0u            // 128 x 512 fp16 = 131072
#define SM_B     131072u       // 3 stages x 16384 (128n x 64k fp16)
#define SM_BIAS  180224u       // 4096 floats = 16384
#define SM_RED   196608u       // 2 x 512 floats = 4096
#define SM_TOT   200704u

// ---------------- device scratch ----------------
__device__ __align__(16) __half g_Wh[(size_t)Vn*Dn];
__device__ float g_pE0[ROWS];
__device__ float g_pE1[ROWS];   // stays 0 for unsplit mtiles (never written)
__device__ float g_pR0[ROWS];
__device__ float g_pR1[ROWS];
__device__ float g_blank[ROWS];
__device__ float g_tgt[ROWS];
__device__ float g_part[Bn];
__device__ unsigned g_done;

// ---------------- helpers ----------------
__device__ __forceinline__ uint32_t smem_u32(const void* p) {
    uint32_t a;
    asm("{ .reg .u64 t; cvta.to.shared.u64 t, %1; cvt.u32.u64 %0, t; }" : "=r"(a) : "l"(p));
    return a;
}
__device__ __forceinline__ void cpa16(uint32_t dst, const void* src) {
    asm volatile("cp.async.cg.shared.global [%0], [%1], 16;" :: "r"(dst), "l"(src));
}
__device__ __forceinline__ void lds128(uint32_t* r, uint32_t addr) {
    asm volatile("ld.shared.v4.b32 {%0,%1,%2,%3}, [%4];"
        : "=r"(r[0]), "=r"(r[1]), "=r"(r[2]), "=r"(r[3]) : "r"(addr));
}
__device__ __forceinline__ __half2 h2(uint32_t v) {
    return *reinterpret_cast<__half2*>(&v);
}
// fast 2^z, FFMA-only (no MUFU). |rel err| ~2e-6.
__device__ __forceinline__ float exp2_fast(float z) {
    float zc = z + 12582912.f;
    int   ni = __float_as_int(zc);
    float n  = zc - 12582912.f;
    float f  = z - n;
    float p  = fmaf(0.0013333558f, f, 0.0096181291f);
    p = fmaf(p, f, 0.0555041087f);
    p = fmaf(p, f, 0.2402265069f);
    p = fmaf(p, f, 0.6931471806f);
    p = fmaf(p, f, 1.0f);
    return __int_as_float(__float_as_int(p) + (ni << 23));
}

// ---------------------------------------------------------------------------
// Kernel 0: convert W fp32 -> fp16
// ---------------------------------------------------------------------------
__global__ void __launch_bounds__(256) convW_kernel(const float* __restrict__ w)
{
    int i = blockIdx.x * 256 + threadIdx.x;          // each handles 8 floats
    const float4* src = reinterpret_cast<const float4*>(w) + (size_t)i * 2;
    float4 v0 = src[0], v1 = src[1];
    __half2 p0 = __floats2half2_rn(v0.x, v0.y);
    __half2 p1 = __floats2half2_rn(v0.z, v0.w);
    __half2 p2 = __floats2half2_rn(v1.x, v1.y);
    __half2 p3 = __floats2half2_rn(v1.z, v1.w);
    uint4 o;
    o.x = *reinterpret_cast<uint32_t*>(&p0);
    o.y = *reinterpret_cast<uint32_t*>(&p1);
    o.z = *reinterpret_cast<uint32_t*>(&p2);
    o.w = *reinterpret_cast<uint32_t*>(&p3);
    *reinterpret_cast<uint4*>(g_Wh + (size_t)i * 8) = o;
}

// ---------------------------------------------------------------------------
// Kernel 1: persistent fp16 mma.sync GEMM + HFMA2 k-offload + fused statistics
//   148 CTAs x 256 threads; static unit partition over (mtile, vtile)
//   Per unit: chunks 0-6 on tensor pipe (HMMA), chunk 7 on fma pipe (HFMA2)
// ---------------------------------------------------------------------------
extern __shared__ char dynsm[];

__device__ __forceinline__ void load_Bchunk(uint32_t Bs, int cg, int stage, int tid)
{
    const __half* wsrc = g_Wh + ((size_t)(cg >> 3)) * 128 * Dn + (cg & 7) * 64;
    const uint32_t dstb = Bs + (uint32_t)stage * 16384u;
#pragma unroll
    for (int it = 0; it < 4; it++) {
        int idx = tid + it * 256;
        int n = idx >> 3, cc = idx & 7;
        cpa16(dstb + n * 128 + ((cc ^ (n & 7))) * 16, wsrc + (size_t)n * Dn + cc * 8);
    }
}

__global__ void __launch_bounds__(256, 1) maingemm_kernel(
    const float* __restrict__ x, const float* __restrict__ bias,
    const int* __restrict__ targets)
{
    const int tid  = threadIdx.x;
    const int lane = tid & 31;
    const int w    = tid >> 5;
    const int wm   = w >> 2;          // 0..1  (64 rows each)
    const int wn   = w & 3;           // 0..3  (32 cols each)
    const int cta  = blockIdx.x;

    const uint32_t sb = smem_u32(dynsm);
    const uint32_t As = sb + SM_A;
    const uint32_t Bs = sb + SM_B;
    float* sbias = (float*)(dynsm + SM_BIAS);
    float* lseb  = (float*)(dynsm + SM_RED);
    float* rawb  = (float*)(dynsm + SM_RED + 2048);

    // ---- bias -> smem once per persistent CTA ----
#pragma unroll
    for (int q = 0; q < 4; q++)
        ((float4*)sbias)[tid + q * 256] = ((const float4*)bias)[tid + q * 256];

    // ---- static work partition ----
    int u, uend;
    if (cta < UREM) { u = cta * (UBASE + 1); uend = u + UBASE + 1; }
    else            { u = UREM * (UBASE + 1) + (cta - UREM) * UBASE; uend = u + UBASE; }

    // ---- per-lane ldmatrix bases (fragment-invariant) ----
    const int arow = wm * 64 + (lane & 15);
    const uint32_t aBase = As + arow * 1024;
    const int alow = lane >> 4;
    const int arx  = arow & 7;
    const int bn   = wn * 32 + ((lane >> 4) << 3) + (lane & 7);
    const int bko  = (lane >> 3) & 1;
    const int bnx  = bn & 7;
    const bool blankown = (wn == 0) && ((lane & 3) == 0);

    // local row ids for this thread's 8 fragment rows (mtile-relative)
    int lrow[8];
#pragma unroll
    for (int i = 0; i < 8; i++) {
        int mtl = i >> 1, hh = i & 1;
        lrow[i] = wm * 64 + mtl * 16 + (lane >> 2) + hh * 8;
    }
    // col bases for the 4 nt pairs
    int cbase2[4];
#pragma unroll
    for (int nt = 0; nt < 4; nt++) cbase2[nt] = wn * 32 + nt * 8 + (lane & 3) * 2;

    uint32_t acc[4][4][2];
#pragma unroll
    for (int a0 = 0; a0 < 4; a0++)
#pragma unroll
        for (int b0 = 0; b0 < 4; b0++) { acc[a0][b0][0] = 0u; acc[a0][b0][1] = 0u; }
    __half2 offacc[8][4];
#pragma unroll
    for (int i = 0; i < 8; i++)
#pragma unroll
        for (int nt = 0; nt < 4; nt++) offacc[i][nt] = __half2half2(__ushort_as_half(0));
    float se[8], sr[8];
#pragma unroll
    for (int i = 0; i < 8; i++) { se[i] = 0.f; sr[i] = 0.f; }

    while (u < uend) {
        const int mt  = u >> 5;
        const int vt0 = u & 31;
        int nvt = 32 - vt0;
        if (uend - u < nvt) nvt = uend - u;
        const int row0   = mt * 128;
        const int nch    = nvt * 8;
        const int cstart = vt0 * 8;

        // ---- per-fragment row ids + target selectors ----
        int grow[8]; int tkey[8]; int tlo[8];
#pragma unroll
        for (int i = 0; i < 8; i++) {
            int gr = row0 + lrow[i];
            grow[i] = gr;
            int b = gr / BTU, rem = gr % BTU, uu = rem % U1n;
            int tv = (uu < U1n - 1) ? targets[b * (U1n - 1) + uu] : -1;
            int key = -1, lo = 0;
            if (tv >= 0 && ((tv >> 5) & 3) == wn && (((tv >> 1) & 3) == (lane & 3))) {
                key = tv >> 3;
                lo  = tv & 1;
            }
            tkey[i] = key; tlo[i] = lo;
        }

        // ---- B prologue (stages 0,1) ----
        load_Bchunk(Bs, cstart, 0, tid);
        asm volatile("cp.async.commit_group;" ::: "memory");
        load_Bchunk(Bs, cstart + 1, 1, tid);
        asm volatile("cp.async.commit_group;" ::: "memory");

        // ---- fill A: fp32 -> fp16 into swizzled smem ----
#pragma unroll 4
        for (int it = 0; it < 32; it++) {
            int idx = tid + it * 256;
            int r = idx >> 6, ch = idx & 63;
            const float4* src = reinterpret_cast<const float4*>(
                x + (size_t)(row0 + r) * Dn + ch * 8);
            float4 v0 = src[0], v1 = src[1];
            __half2 p0 = __floats2half2_rn(v0.x, v0.y);
            __half2 p1 = __floats2half2_rn(v0.z, v0.w);
            __half2 p2 = __floats2half2_rn(v1.x, v1.y);
            __half2 p3 = __floats2half2_rn(v1.z, v1.w);
            uint32_t dchunk = (uint32_t)((ch & ~7) | ((ch ^ r) & 7));
            uint32_t dst = As + r * 1024 + dchunk * 16;
            asm volatile("st.shared.v4.b32 [%0], {%1,%2,%3,%4};" ::
                "r"(dst),
                "r"(*reinterpret_cast<uint32_t*>(&p0)), "r"(*reinterpret_cast<uint32_t*>(&p1)),
                "r"(*reinterpret_cast<uint32_t*>(&p2)), "r"(*reinterpret_cast<uint32_t*>(&p3))
                : "memory");
        }

        for (int ct = 0; ct < nch; ct++) {
            const int cg = cstart + ct;
            const int vt = cg >> 3, kc = cg & 7, st = ct % 3;
            __syncthreads();                       // stage (ct+2)%3 free / A-fill barrier
            if (ct + 2 < nch) {
                load_Bchunk(Bs, cstart + ct + 2, (ct + 2) % 3, tid);
                asm volatile("cp.async.commit_group;" ::: "memory");
                asm volatile("cp.async.wait_group 2;" ::: "memory");
            } else if (ct + 1 < nch) {
                asm volatile("cp.async.wait_group 1;" ::: "memory");
            } else {
                asm volatile("cp.async.wait_group 0;" ::: "memory");
            }
            __syncthreads();                       // chunk ct visible

            if (kc < 7) {
                // ================= tensor-pipe path (chunks 0-6) =================
                const uint32_t aCh = aBase + kc * 128;
                const uint32_t bSt = Bs + (uint32_t)st * 16384u + bn * 128;
#pragma unroll
                for (int ks = 0; ks < 4; ks++) {
                    uint32_t afr[4][4];
#pragma unroll
                    for (int mtl = 0; mtl < 4; mtl++) {
                        uint32_t ad = aCh + mtl * 16384 + (uint32_t)(((ks * 2 + alow) ^ arx)) * 16;
                        asm volatile("ldmatrix.sync.aligned.m8n8.x4.shared.b16 {%0,%1,%2,%3}, [%4];"
                            : "=r"(afr[mtl][0]), "=r"(afr[mtl][1]), "=r"(afr[mtl][2]), "=r"(afr[mtl][3])
                            : "r"(ad));
                    }
                    uint32_t bfr[2][4];
#pragma unroll
                    for (int np = 0; np < 2; np++) {
                        uint32_t bd = bSt + np * 2048 + (uint32_t)(((ks * 2 + bko) ^ bnx)) * 16;
                        asm volatile("ldmatrix.sync.aligned.m8n8.x4.shared.b16 {%0,%1,%2,%3}, [%4];"
                            : "=r"(bfr[np][0]), "=r"(bfr[np][1]), "=r"(bfr[np][2]), "=r"(bfr[np][3])
                            : "r"(bd));
                    }
#pragma unroll
                    for (int mtl = 0; mtl < 4; mtl++)
#pragma unroll
                        for (int nt = 0; nt < 4; nt++) {
                            asm volatile("mma.sync.aligned.m16n8k16.row.col.f16.f16.f16.f16 "
                                "{%0,%1}, {%2,%3,%4,%5}, {%6,%7}, {%0,%1};"
                                : "+r"(acc[mtl][nt][0]), "+r"(acc[mtl][nt][1])
                                : "r"(afr[mtl][0]), "r"(afr[mtl][1]), "r"(afr[mtl][2]), "r"(afr[mtl][3]),
                                  "r"(bfr[nt >> 1][(nt & 1) * 2]), "r"(bfr[nt >> 1][(nt & 1) * 2 + 1]));
                        }
                }
            } else {
                // ================= fma-pipe path (chunk 7, k in [448,512)) =======
                const uint32_t bSt = Bs + (uint32_t)st * 16384u;
#pragma unroll
                for (int cc = 0; cc < 8; cc++) {
                    uint32_t b0r[4][4], b1r[4][4];
#pragma unroll
                    for (int nt = 0; nt < 4; nt++) {
                        int c0 = cbase2[nt];
                        lds128(b0r[nt], bSt + c0 * 128 + ((cc ^ (c0 & 7)) * 16));
                        lds128(b1r[nt], bSt + (c0 + 1) * 128 + ((cc ^ ((c0 + 1) & 7)) * 16));
                    }
#pragma unroll
                    for (int hf = 0; hf < 2; hf++) {
                        uint32_t a4[4][4];
#pragma unroll
                        for (int rr = 0; rr < 4; rr++) {
                            int lr = lrow[hf * 4 + rr];
                            lds128(a4[rr], As + lr * 1024 + 896 + ((cc ^ (lr & 7)) * 16));
                        }
#pragma unroll
                        for (int kk = 0; kk < 4; kk++) {
                            __half2 bl[4], bh[4];
#pragma unroll
                            for (int nt = 0; nt < 4; nt++) {
                                bl[nt] = __lows2half2(h2(b0r[nt][kk]), h2(b1r[nt][kk]));
                                bh[nt] = __highs2half2(h2(b0r[nt][kk]), h2(b1r[nt][kk]));
                            }
#pragma unroll
                            for (int rr = 0; rr < 4; rr++) {
                                __half2 a2 = h2(a4[rr][kk]);
                                __half2 alo = __half2half2(__low2half(a2));
                                __half2 ahi = __half2half2(__high2half(a2));
#pragma unroll
                                for (int nt = 0; nt < 4; nt++) {
                                    offacc[hf * 4 + rr][nt] = __hfma2(alo, bl[nt], offacc[hf * 4 + rr][nt]);
                                    offacc[hf * 4 + rr][nt] = __hfma2(ahi, bh[nt], offacc[hf * 4 + rr][nt]);
                                }
                            }
                        }
                    }
                }

                // ---- register-only epilogue for vtile vt ----
                float bcol[8];
#pragma unroll
                for (int nt = 0; nt < 4; nt++) {
                    bcol[nt * 2]     = sbias[vt * 128 + cbase2[nt]];
                    bcol[nt * 2 + 1] = sbias[vt * 128 + cbase2[nt] + 1];
                }
                const int vbase = vt * 16 + wn * 4;
#pragma unroll
                for (int mtl = 0; mtl < 4; mtl++)
#pragma unroll
                    for (int hh = 0; hh < 2; hh++) {
                        const int i = mtl * 2 + hh;
#pragma unroll
                        for (int nt = 0; nt < 4; nt++) {
                            uint32_t pk = acc[mtl][nt][hh];
                            float2 fv = __half22float2(*reinterpret_cast<__half2*>(&pk));
                            float2 fo = __half22float2(offacc[i][nt]);
#pragma unroll
                            for (int lo = 0; lo < 2; lo++) {
                                float y = (lo ? fv.y : fv.x) + (lo ? fo.y : fo.x) + bcol[nt * 2 + lo];
                                sr[i] += y;
                                se[i] += exp2_fast(y * L2E);
                                if (tkey[i] == vbase + nt && tlo[i] == lo)
                                    g_tgt[grow[i]] = y;
                                if (vt == 0 && nt == 0 && lo == 0 && blankown)
                                    g_blank[grow[i]] = y;
                            }
                        }
                    }
#pragma unroll
                for (int a0 = 0; a0 < 4; a0++)
#pragma unroll
                    for (int b0 = 0; b0 < 4; b0++) { acc[a0][b0][0] = 0u; acc[a0][b0][1] = 0u; }
#pragma unroll
                for (int i = 0; i < 8; i++)
#pragma unroll
                    for (int nt = 0; nt < 4; nt++) offacc[i][nt] = __half2half2(__ushort_as_half(0));
            }
        }

        // ---- fragment partial reduction + slotted write ----
#pragma unroll
        for (int i = 0; i < 8; i++) {
            se[i] += __shfl_xor_sync(0xffffffffu, se[i], 1);
            se[i] += __shfl_xor_sync(0xffffffffu, se[i], 2);
            sr[i] += __shfl_xor_sync(0xffffffffu, sr[i], 1);
            sr[i] += __shfl_xor_sync(0xffffffffu, sr[i], 2);
        }
        __syncthreads();
        if ((lane & 3) == 0) {
#pragma unroll
            for (int i = 0; i < 8; i++) {
                lseb[wn * 128 + lrow[i]] = se[i];
                rawb[wn * 128 + lrow[i]] = sr[i];
            }
        }
        __syncthreads();
        if (tid < 128) {
            float E = (lseb[tid] + lseb[128 + tid]) + (lseb[256 + tid] + lseb[384 + tid]);
            float R = (rawb[tid] + rawb[128 + tid]) + (rawb[256 + tid] + rawb[384 + tid]);
            if (vt0 == 0) { g_pE0[row0 + tid] = E; g_pR0[row0 + tid] = R; }
            else          { g_pE1[row0 + tid] = E; g_pR1[row0 + tid] = R; }
        }
#pragma unroll
        for (int i = 0; i < 8; i++) { se[i] = 0.f; sr[i] = 0.f; }

        u += nvt;
    }
}

// ---------------------------------------------------------------------------
// Kernel 2: per-batch DP (smem-staged) + label-smoothed CE + final sum
// ---------------------------------------------------------------------------
__device__ __forceinline__ float laddexp(float a, float b) {
    float m = fmaxf(a, b);
    return m + log1pf(__expf(-fabsf(a - b)));
}

__global__ void __launch_bounds__(256) finalize_kernel(
    const int* __restrict__ targets,
    const int* __restrict__ src_lengths,
    const int* __restrict__ tgt_lengths,
    float* __restrict__ out)
{
    __shared__ float sbl[BTU];
    __shared__ float sem[BTU];
    __shared__ float s_dp;
    const int b = blockIdx.x;
    const int tid = threadIdx.x;
    const int base = b * BTU;

    for (int i = tid; i < BTU; i += 256) {
        float E = g_pE0[base + i] + g_pE1[base + i];
        float l = logf(E);
        sbl[i] = g_blank[base + i] - l;
        sem[i] = g_tgt[base + i] - l;
    }
    __syncthreads();

    if (tid < 32) {
        const int lane = tid;
        const int S  = src_lengths[b];
        const int TG = tgt_lengths[b];
        float cur = 0.f, cur2 = 0.f, afin = 0.f;
        bool have = false;
        const int nsteps = (S - 1) + 32;
        for (int s = 0; s <= nsteps; s++) {
            float left   = __shfl_up_sync(0xffffffffu, cur, 1);
            float prev31 = cur;
            int t = s - lane;
            if (t >= 0 && t <= S - 1) {
                int uu = lane;
                if (t == 0) {
                    cur = (uu == 0) ? 0.f : left + sem[uu - 1];
                } else {
                    float up = cur + sbl[(t - 1) * U1n + uu];
                    cur = (uu == 0) ? up : laddexp(up, left + sem[t * U1n + (uu - 1)]);
                }
                if (t == S - 1 && uu == TG) { afin = cur; have = true; }
            }
            if (lane == 31) {
                int t2 = s - 32;
                if (t2 >= 0 && t2 <= S - 1) {
                    float lft = prev31 + sem[t2 * U1n + 31];
                    cur2 = (t2 == 0) ? lft : laddexp(cur2 + sbl[(t2 - 1) * U1n + 32], lft);
                    if (t2 == S - 1 && TG == 32) { afin = cur2; have = true; }
                }
            }
        }
        float lossb = have ? -(afin + sbl[(S - 1) * U1n + TG]) : 0.f;
#pragma unroll
        for (int o = 16; o > 0; o >>= 1)
            lossb += __shfl_xor_sync(0xffffffffu, lossb, o);
        if (lane == 0) s_dp = lossb;
    }
    __syncthreads();

    if (tid < 32) {
        const int uu = tid;
        const int S = src_lengths[b];
        const int tv = targets[b * (U1n - 1) + uu];
        const int row = b * BTU + (S - 1) * U1n + uu;
        float E = g_pE0[row] + g_pE1[row];
        float lse = logf(E);
        float R = g_pR0[row] + g_pR1[row];
        float nll = lse - g_tgt[row];
        float smooth = (float)Vn * lse - R;
        const float LS = 0.1f;
        const float eps = LS / (float)(Vn - 1);
        float m = (tv != 1) ? 1.f : 0.f;
        float term = ((1.f - LS - eps) * nll + eps * smooth) * m;
#pragma unroll
        for (int o = 16; o > 0; o >>= 1)
            term += __shfl_xor_sync(0xffffffffu, term, o);
        if (uu == 0) {
            g_part[b] = s_dp + term;
            __threadfence();
            unsigned t = atomicAdd(&g_done, 1u);
            if (t == (unsigned)(Bn - 1)) {
                __threadfence();
                float s = 0.f;
#pragma unroll
                for (int bb = 0; bb < Bn; bb++) s += g_part[bb];
                out[0] = s;
                g_done = 0u;           // reset for next graph replay
            }
        }
    }
}

// ---------------------------------------------------------------------------
extern "C" void kernel_launch(void* const* d_in, const int* in_sizes, int n_in,
                              void* d_out, int out_size)
{
    const float* x       = (const float*)d_in[0];
    const float* wgt     = (const float*)d_in[1];
    const float* bias    = (const float*)d_in[2];
    const int*   targets = (const int*)d_in[3];
    const int*   src     = (const int*)d_in[4];
    const int*   tgt     = (const int*)d_in[5];
    float* out = (float*)d_out;

    static bool attr_set = false;
    if (!attr_set) {
        cudaFuncSetAttribute(maingemm_kernel,
                             cudaFuncAttributeMaxDynamicSharedMemorySize, SM_TOT);
        attr_set = true;
    }

    convW_kernel<<<(Vn * Dn / 8) / 256, 256>>>(wgt);
    maingemm_kernel<<<NCTA, 256, SM_TOT>>>(x, bias, targets);
    finalize_kernel<<<Bn, 256>>>(targets, src, tgt, out);
}

// round 12
// speedup vs baseline: 2.2381x; 2.2381x over previous
#include <cuda_runtime.h>
#include <cuda_fp16.h>
#include <math.h>
#include <stdint.h>

#define Bn   8
#define Tn   128
#define U1n  33
#define Dn   512
#define Vn   4096
#define BTU  (Tn*U1n)          // 4224
#define ROWS (Bn*BTU)          // 33792
#define MTL  (ROWS/128)        // 264 M-tiles (33 per batch)
#define NVT  (Vn/128)          // 32 vocab tiles
#define NCTA 148
#define L2E  1.442695040888963f

// smem layout (bytes)
#define SM_A     0u            // 128 x 512 fp16 = 131072
#define SM_B     131072u       // 3 stages x 16384 (128n x 64k fp16)
#define SM_BIAS  180224u       // 4096 floats = 16384
#define SM_RED   196608u       // 2 x 512 floats = 4096
#define SM_TOT   200704u

// ---------------- device scratch ----------------
__device__ __align__(16) __half g_Wh[(size_t)Vn*Dn];
__device__ float g_pE0[ROWS];   // start segments (vt0 == 0)
__device__ float g_pE1[ROWS];   // end segments (vt0 > 0, reaches vtile 31)
__device__ float g_pE2[ROWS];   // middle segments (rare 3-way splits)
__device__ float g_pR0[ROWS];
__device__ float g_pR1[ROWS];
__device__ float g_pR2[ROWS];
__device__ float g_blank[ROWS];
__device__ float g_tgt[ROWS];
__device__ float g_part[Bn];
__device__ unsigned g_done;
__device__ int g_mtlist[MTL];          // useful mtile ids
__device__ int g_ustart[NCTA + 1];     // per-CTA unit ranges

// ---------------- helpers ----------------
__device__ __forceinline__ uint32_t smem_u32(const void* p) {
    uint32_t a;
    asm("{ .reg .u64 t; cvta.to.shared.u64 t, %1; cvt.u32.u64 %0, t; }" : "=r"(a) : "l"(p));
    return a;
}
__device__ __forceinline__ void cpa16(uint32_t dst, const void* src) {
    asm volatile("cp.async.cg.shared.global [%0], [%1], 16;" :: "r"(dst), "l"(src));
}
// fast 2^z, FFMA-only (no MUFU). |rel err| ~2e-6.
__device__ __forceinline__ float exp2_fast(float z) {
    float zc = z + 12582912.f;
    int   ni = __float_as_int(zc);
    float n  = zc - 12582912.f;
    float f  = z - n;
    float p  = fmaf(0.0013333558f, f, 0.0096181291f);
    p = fmaf(p, f, 0.0555041087f);
    p = fmaf(p, f, 0.2402265069f);
    p = fmaf(p, f, 0.6931471806f);
    p = fmaf(p, f, 1.0f);
    return __int_as_float(__float_as_int(p) + (ni << 23));
}

// ---------------------------------------------------------------------------
// Kernel 0: convert W fp32 -> fp16
// ---------------------------------------------------------------------------
__global__ void __launch_bounds__(256) convW_kernel(const float* __restrict__ w)
{
    int i = blockIdx.x * 256 + threadIdx.x;          // each handles 8 floats
    const float4* src = reinterpret_cast<const float4*>(w) + (size_t)i * 2;
    float4 v0 = src[0], v1 = src[1];
    __half2 p0 = __floats2half2_rn(v0.x, v0.y);
    __half2 p1 = __floats2half2_rn(v0.z, v0.w);
    __half2 p2 = __floats2half2_rn(v1.x, v1.y);
    __half2 p3 = __floats2half2_rn(v1.z, v1.w);
    uint4 o;
    o.x = *reinterpret_cast<uint32_t*>(&p0);
    o.y = *reinterpret_cast<uint32_t*>(&p1);
    o.z = *reinterpret_cast<uint32_t*>(&p2);
    o.w = *reinterpret_cast<uint32_t*>(&p3);
    *reinterpret_cast<uint4*>(g_Wh + (size_t)i * 8) = o;
}

// ---------------------------------------------------------------------------
// Kernel 0b: build useful-mtile list + balanced per-CTA unit partition.
// Deterministic (function of src_lengths only) -> identical every replay.
// ---------------------------------------------------------------------------
__global__ void schedule_kernel(const int* __restrict__ src)
{
    if (threadIdx.x != 0) return;
    int S[Bn];
#pragma unroll
    for (int b = 0; b < Bn; b++) S[b] = src[b];
    int n = 0;
    for (int mt = 0; mt < MTL; mt++) {
        int b = mt / 33, m = mt % 33;
        if ((m * 128) / 33 < S[b]) g_mtlist[n++] = mt;   // mtile has a row with t < S
    }
    int utot = n * NVT;
    int ub = utot / NCTA, ur = utot % NCTA;
    int acc = 0;
    for (int c = 0; c <= NCTA; c++) {
        g_ustart[c] = acc;
        acc += ub + (c < ur ? 1 : 0);
    }
}

// ---------------------------------------------------------------------------
// Kernel 1: persistent fp16 mma.sync GEMM + fused statistics
//   148 CTAs x 256 threads; length-aware unit partition over (mtile, vtile)
// ---------------------------------------------------------------------------
extern __shared__ char dynsm[];

__device__ __forceinline__ void load_Bchunk(uint32_t Bs, int cg, int stage, int tid)
{
    const __half* wsrc = g_Wh + ((size_t)(cg >> 3)) * 128 * Dn + (cg & 7) * 64;
    const uint32_t dstb = Bs + (uint32_t)stage * 16384u;
#pragma unroll
    for (int it = 0; it < 4; it++) {
        int idx = tid + it * 256;
        int n = idx >> 3, cc = idx & 7;
        cpa16(dstb + n * 128 + ((cc ^ (n & 7))) * 16, wsrc + (size_t)n * Dn + cc * 8);
    }
}

__global__ void __launch_bounds__(256, 1) maingemm_kernel(
    const float* __restrict__ x, const float* __restrict__ bias,
    const int* __restrict__ targets)
{
    const int tid  = threadIdx.x;
    const int lane = tid & 31;
    const int w    = tid >> 5;
    const int wm   = w >> 2;          // 0..1  (64 rows each)
    const int wn   = w & 3;           // 0..3  (32 cols each)
    const int cta  = blockIdx.x;

    const uint32_t sb = smem_u32(dynsm);
    const uint32_t As = sb + SM_A;
    const uint32_t Bs = sb + SM_B;
    float* sbias = (float*)(dynsm + SM_BIAS);
    float* lseb  = (float*)(dynsm + SM_RED);
    float* rawb  = (float*)(dynsm + SM_RED + 2048);

    // ---- bias -> smem once per persistent CTA ----
#pragma unroll
    for (int q = 0; q < 4; q++)
        ((float4*)sbias)[tid + q * 256] = ((const float4*)bias)[tid + q * 256];

    // ---- length-aware work partition (from schedule_kernel) ----
    int u    = g_ustart[cta];
    int uend = g_ustart[cta + 1];

    // ---- per-lane ldmatrix bases (fragment-invariant) ----
    const int arow = wm * 64 + (lane & 15);
    const uint32_t aBase = As + arow * 1024;
    const int alow = lane >> 4;
    const int arx  = arow & 7;
    const int bn   = wn * 32 + ((lane >> 4) << 3) + (lane & 7);
    const int bko  = (lane >> 3) & 1;
    const int bnx  = bn & 7;
    const bool blankown = (wn == 0) && ((lane & 3) == 0);

    uint32_t acc[4][4][2];
#pragma unroll
    for (int a0 = 0; a0 < 4; a0++)
#pragma unroll
        for (int b0 = 0; b0 < 4; b0++) { acc[a0][b0][0] = 0u; acc[a0][b0][1] = 0u; }
    float se[8], sr[8];
#pragma unroll
    for (int i = 0; i < 8; i++) { se[i] = 0.f; sr[i] = 0.f; }

    while (u < uend) {
        const int mt  = g_mtlist[u >> 5];
        const int vt0 = u & 31;
        int nvt = 32 - vt0;
        if (uend - u < nvt) nvt = uend - u;
        const int row0   = mt * 128;
        const int nch    = nvt * 8;
        const int cstart = vt0 * 8;

        // ---- per-fragment row ids + target selectors ----
        int grow[8]; int tkey[8]; int tlo[8];
#pragma unroll
        for (int i = 0; i < 8; i++) {
            int mtl = i >> 1, h = i & 1;
            int gr = row0 + wm * 64 + mtl * 16 + (lane >> 2) + h * 8;
            grow[i] = gr;
            int b = gr / BTU, rem = gr % BTU, uu = rem % U1n;
            int tv = (uu < U1n - 1) ? targets[b * (U1n - 1) + uu] : -1;
            int key = -1, lo = 0;
            if (tv >= 0 && ((tv >> 5) & 3) == wn && (((tv >> 1) & 3) == (lane & 3))) {
                key = tv >> 3;
                lo  = tv & 1;
            }
            tkey[i] = key; tlo[i] = lo;
        }

        // ---- B prologue (stages 0,1) ----
        load_Bchunk(Bs, cstart, 0, tid);
        asm volatile("cp.async.commit_group;" ::: "memory");
        load_Bchunk(Bs, cstart + 1, 1, tid);
        asm volatile("cp.async.commit_group;" ::: "memory");

        // ---- fill A: fp32 -> fp16 into swizzled smem ----
#pragma unroll 4
        for (int it = 0; it < 32; it++) {
            int idx = tid + it * 256;
            int r = idx >> 6, ch = idx & 63;
            const float4* src = reinterpret_cast<const float4*>(
                x + (size_t)(row0 + r) * Dn + ch * 8);
            float4 v0 = src[0], v1 = src[1];
            __half2 p0 = __floats2half2_rn(v0.x, v0.y);
            __half2 p1 = __floats2half2_rn(v0.z, v0.w);
            __half2 p2 = __floats2half2_rn(v1.x, v1.y);
            __half2 p3 = __floats2half2_rn(v1.z, v1.w);
            uint32_t dchunk = (uint32_t)((ch & ~7) | ((ch ^ r) & 7));
            uint32_t dst = As + r * 1024 + dchunk * 16;
            asm volatile("st.shared.v4.b32 [%0], {%1,%2,%3,%4};" ::
                "r"(dst),
                "r"(*reinterpret_cast<uint32_t*>(&p0)), "r"(*reinterpret_cast<uint32_t*>(&p1)),
                "r"(*reinterpret_cast<uint32_t*>(&p2)), "r"(*reinterpret_cast<uint32_t*>(&p3))
                : "memory");
        }

        for (int ct = 0; ct < nch; ct++) {
            const int cg = cstart + ct;
            const int vt = cg >> 3, kc = cg & 7, st = ct % 3;
            __syncthreads();                       // stage (ct+2)%3 free / A-fill barrier
            if (ct + 2 < nch) {
                load_Bchunk(Bs, cstart + ct + 2, (ct + 2) % 3, tid);
                asm volatile("cp.async.commit_group;" ::: "memory");
                asm volatile("cp.async.wait_group 2;" ::: "memory");
            } else if (ct + 1 < nch) {
                asm volatile("cp.async.wait_group 1;" ::: "memory");
            } else {
                asm volatile("cp.async.wait_group 0;" ::: "memory");
            }
            __syncthreads();                       // chunk ct visible

            const uint32_t aCh = aBase + kc * 128;
            const uint32_t bSt = Bs + (uint32_t)st * 16384u + bn * 128;
#pragma unroll
            for (int ks = 0; ks < 4; ks++) {
                uint32_t afr[4][4];
#pragma unroll
                for (int mtl = 0; mtl < 4; mtl++) {
                    uint32_t ad = aCh + mtl * 16384 + (uint32_t)(((ks * 2 + alow) ^ arx)) * 16;
                    asm volatile("ldmatrix.sync.aligned.m8n8.x4.shared.b16 {%0,%1,%2,%3}, [%4];"
                        : "=r"(afr[mtl][0]), "=r"(afr[mtl][1]), "=r"(afr[mtl][2]), "=r"(afr[mtl][3])
                        : "r"(ad));
                }
                uint32_t bfr[2][4];
#pragma unroll
                for (int np = 0; np < 2; np++) {
                    uint32_t bd = bSt + np * 2048 + (uint32_t)(((ks * 2 + bko) ^ bnx)) * 16;
                    asm volatile("ldmatrix.sync.aligned.m8n8.x4.shared.b16 {%0,%1,%2,%3}, [%4];"
                        : "=r"(bfr[np][0]), "=r"(bfr[np][1]), "=r"(bfr[np][2]), "=r"(bfr[np][3])
                        : "r"(bd));
                }
#pragma unroll
                for (int mtl = 0; mtl < 4; mtl++)
#pragma unroll
                    for (int nt = 0; nt < 4; nt++) {
                        asm volatile("mma.sync.aligned.m16n8k16.row.col.f16.f16.f16.f16 "
                            "{%0,%1}, {%2,%3,%4,%5}, {%6,%7}, {%0,%1};"
                            : "+r"(acc[mtl][nt][0]), "+r"(acc[mtl][nt][1])
                            : "r"(afr[mtl][0]), "r"(afr[mtl][1]), "r"(afr[mtl][2]), "r"(afr[mtl][3]),
                              "r"(bfr[nt >> 1][(nt & 1) * 2]), "r"(bfr[nt >> 1][(nt & 1) * 2 + 1]));
                    }
            }

            if (kc == 7) {
                // ---- register-only epilogue for vtile vt ----
                float bcol[8];
#pragma unroll
                for (int nt = 0; nt < 4; nt++) {
                    bcol[nt * 2]     = sbias[vt * 128 + wn * 32 + nt * 8 + (lane & 3) * 2];
                    bcol[nt * 2 + 1] = sbias[vt * 128 + wn * 32 + nt * 8 + (lane & 3) * 2 + 1];
                }
                const int vbase = vt * 16 + wn * 4;
#pragma unroll
                for (int mtl = 0; mtl < 4; mtl++)
#pragma unroll
                    for (int h = 0; h < 2; h++) {
                        const int i = mtl * 2 + h;
#pragma unroll
                        for (int nt = 0; nt < 4; nt++) {
                            uint32_t pk = acc[mtl][nt][h];
                            float2 fv = __half22float2(*reinterpret_cast<__half2*>(&pk));
#pragma unroll
                            for (int lo = 0; lo < 2; lo++) {
                                float y = (lo ? fv.y : fv.x) + bcol[nt * 2 + lo];
                                sr[i] += y;
                                se[i] += exp2_fast(y * L2E);
                                if (tkey[i] == vbase + nt && tlo[i] == lo)
                                    g_tgt[grow[i]] = y;
                                if (vt == 0 && nt == 0 && lo == 0 && blankown)
                                    g_blank[grow[i]] = y;
                            }
                        }
                    }
#pragma unroll
                for (int a0 = 0; a0 < 4; a0++)
#pragma unroll
                    for (int b0 = 0; b0 < 4; b0++) { acc[a0][b0][0] = 0u; acc[a0][b0][1] = 0u; }
            }
        }

        // ---- fragment partial reduction + slotted write ----
#pragma unroll
        for (int i = 0; i < 8; i++) {
            se[i] += __shfl_xor_sync(0xffffffffu, se[i], 1);
            se[i] += __shfl_xor_sync(0xffffffffu, se[i], 2);
            sr[i] += __shfl_xor_sync(0xffffffffu, sr[i], 1);
            sr[i] += __shfl_xor_sync(0xffffffffu, sr[i], 2);
        }
        __syncthreads();
        if ((lane & 3) == 0) {
#pragma unroll
            for (int i = 0; i < 8; i++) {
                int mtl = i >> 1, h = i & 1;
                int lr = wm * 64 + mtl * 16 + (lane >> 2) + h * 8;
                lseb[wn * 128 + lr] = se[i];
                rawb[wn * 128 + lr] = sr[i];
            }
        }
        __syncthreads();
        if (tid < 128) {
            float E = (lseb[tid] + lseb[128 + tid]) + (lseb[256 + tid] + lseb[384 + tid]);
            float R = (rawb[tid] + rawb[128 + tid]) + (rawb[256 + tid] + rawb[384 + tid]);
            // segment -> slot: start / end / middle (3-way splits possible)
            if (vt0 == 0)             { g_pE0[row0 + tid] = E; g_pR0[row0 + tid] = R; }
            else if (vt0 + nvt == 32) { g_pE1[row0 + tid] = E; g_pR1[row0 + tid] = R; }
            else                      { g_pE2[row0 + tid] = E; g_pR2[row0 + tid] = R; }
        }
#pragma unroll
        for (int i = 0; i < 8; i++) { se[i] = 0.f; sr[i] = 0.f; }

        u += nvt;
    }
}

// ---------------------------------------------------------------------------
// Kernel 2: per-batch DP (smem-staged) + label-smoothed CE + final sum
// ---------------------------------------------------------------------------
__device__ __forceinline__ float laddexp(float a, float b) {
    float m = fmaxf(a, b);
    return m + log1pf(__expf(-fabsf(a - b)));
}

__global__ void __launch_bounds__(256) finalize_kernel(
    const int* __restrict__ targets,
    const int* __restrict__ src_lengths,
    const int* __restrict__ tgt_lengths,
    float* __restrict__ out)
{
    __shared__ float sbl[BTU];
    __shared__ float sem[BTU];
    __shared__ float s_dp;
    const int b = blockIdx.x;
    const int tid = threadIdx.x;
    const int base = b * BTU;

    for (int i = tid; i < BTU; i += 256) {
        float E = (g_pE0[base + i] + g_pE1[base + i]) + g_pE2[base + i];
        float l = logf(E);
        sbl[i] = g_blank[base + i] - l;
        sem[i] = g_tgt[base + i] - l;
    }
    __syncthreads();

    if (tid < 32) {
        const int lane = tid;
        const int S  = src_lengths[b];
        const int TG = tgt_lengths[b];
        float cur = 0.f, cur2 = 0.f, afin = 0.f;
        bool have = false;
        const int nsteps = (S - 1) + 32;
        for (int s = 0; s <= nsteps; s++) {
            float left   = __shfl_up_sync(0xffffffffu, cur, 1);
            float prev31 = cur;
            int t = s - lane;
            if (t >= 0 && t <= S - 1) {
                int uu = lane;
                if (t == 0) {
                    cur = (uu == 0) ? 0.f : left + sem[uu - 1];
                } else {
                    float up = cur + sbl[(t - 1) * U1n + uu];
                    cur = (uu == 0) ? up : laddexp(up, left + sem[t * U1n + (uu - 1)]);
                }
                if (t == S - 1 && uu == TG) { afin = cur; have = true; }
            }
            if (lane == 31) {
                int t2 = s - 32;
                if (t2 >= 0 && t2 <= S - 1) {
                    float lft = prev31 + sem[t2 * U1n + 31];
                    cur2 = (t2 == 0) ? lft : laddexp(cur2 + sbl[(t2 - 1) * U1n + 32], lft);
                    if (t2 == S - 1 && TG == 32) { afin = cur2; have = true; }
                }
            }
        }
        float lossb = have ? -(afin + sbl[(S - 1) * U1n + TG]) : 0.f;
#pragma unroll
        for (int o = 16; o > 0; o >>= 1)
            lossb += __shfl_xor_sync(0xffffffffu, lossb, o);
        if (lane == 0) s_dp = lossb;
    }
    __syncthreads();

    if (tid < 32) {
        const int uu = tid;
        const int S = src_lengths[b];
        const int tv = targets[b * (U1n - 1) + uu];
        const int row = b * BTU + (S - 1) * U1n + uu;
        float E = (g_pE0[row] + g_pE1[row]) + g_pE2[row];
        float lse = logf(E);
        float R = (g_pR0[row] + g_pR1[row]) + g_pR2[row];
        float nll = lse - g_tgt[row];
        float smooth = (float)Vn * lse - R;
        const float LS = 0.1f;
        const float eps = LS / (float)(Vn - 1);
        float m = (tv != 1) ? 1.f : 0.f;
        float term = ((1.f - LS - eps) * nll + eps * smooth) * m;
#pragma unroll
        for (int o = 16; o > 0; o >>= 1)
            term += __shfl_xor_sync(0xffffffffu, term, o);
        if (uu == 0) {
            g_part[b] = s_dp + term;
            __threadfence();
            unsigned t = atomicAdd(&g_done, 1u);
            if (t == (unsigned)(Bn - 1)) {
                __threadfence();
                float s = 0.f;
#pragma unroll
                for (int bb = 0; bb < Bn; bb++) s += g_part[bb];
                out[0] = s;
                g_done = 0u;           // reset for next graph replay
            }
        }
    }
}

// ---------------------------------------------------------------------------
extern "C" void kernel_launch(void* const* d_in, const int* in_sizes, int n_in,
                              void* d_out, int out_size)
{
    const float* x       = (const float*)d_in[0];
    const float* wgt     = (const float*)d_in[1];
    const float* bias    = (const float*)d_in[2];
    const int*   targets = (const int*)d_in[3];
    const int*   src     = (const int*)d_in[4];
    const int*   tgt     = (const int*)d_in[5];
    float* out = (float*)d_out;

    static bool attr_set = false;
    if (!attr_set) {
        cudaFuncSetAttribute(maingemm_kernel,
                             cudaFuncAttributeMaxDynamicSharedMemorySize, SM_TOT);
        attr_set = true;
    }

    convW_kernel<<<(Vn * Dn / 8) / 256, 256>>>(wgt);
    schedule_kernel<<<1, 32>>>(src);
    maingemm_kernel<<<NCTA, 256, SM_TOT>>>(x, bias, targets);
    finalize_kernel<<<Bn, 256>>>(targets, src, tgt, out);
}

// round 13
// speedup vs baseline: 2.3581x; 1.0536x over previous
#include <cuda_runtime.h>
#include <cuda_fp16.h>
#include <math.h>
#include <stdint.h>

#define Bn   8
#define Tn   128
#define U1n  33
#define Dn   512
#define Vn   4096
#define BTU  (Tn*U1n)          // 4224
#define ROWS (Bn*BTU)          // 33792
#define MTL  (ROWS/128)        // 264 M-tiles (33 per batch)
#define NVT  (Vn/128)          // 32 vocab tiles
#define NCTA 148
#define L2E  1.442695040888963f
#define LN2  0.6931471805599453f
#define U1P  34                // padded lattice stride (bank-conflict-free)
#define BTUP (Tn*U1P)          // 4352

// smem layout (bytes) for maingemm
#define SM_A     0u            // 128 x 512 fp16 = 131072
#define SM_B     131072u       // 3 stages x 16384 (128n x 64k fp16)
#define SM_BIAS  180224u       // 4096 floats = 16384
#define SM_RED   196608u       // 2 x 512 floats = 4096
#define SM_TOT   200704u

// ---------------- device scratch ----------------
__device__ __align__(16) __half g_Wh[(size_t)Vn*Dn];
__device__ float g_pE0[ROWS];   // start segments (vt0 == 0)
__device__ float g_pE1[ROWS];   // end segments (vt0 > 0, reaches vtile 31)
__device__ float g_pE2[ROWS];   // middle segments (rare 3-way splits)
__device__ float g_pR0[ROWS];
__device__ float g_pR1[ROWS];
__device__ float g_pR2[ROWS];
__device__ float g_blank[ROWS];
__device__ float g_tgt[ROWS];
__device__ float g_part[Bn];
__device__ unsigned g_done;
__device__ int g_mtlist[MTL];          // useful mtile ids
__device__ int g_ustart[NCTA + 1];     // per-CTA unit ranges

// ---------------- helpers ----------------
__device__ __forceinline__ uint32_t smem_u32(const void* p) {
    uint32_t a;
    asm("{ .reg .u64 t; cvta.to.shared.u64 t, %1; cvt.u32.u64 %0, t; }" : "=r"(a) : "l"(p));
    return a;
}
__device__ __forceinline__ void cpa16(uint32_t dst, const void* src) {
    asm volatile("cp.async.cg.shared.global [%0], [%1], 16;" :: "r"(dst), "l"(src));
}
__device__ __forceinline__ float ex2a(float x) {
    float y; asm("ex2.approx.ftz.f32 %0, %1;" : "=f"(y) : "f"(x)); return y;
}
__device__ __forceinline__ float lg2a(float x) {
    float y; asm("lg2.approx.ftz.f32 %0, %1;" : "=f"(y) : "f"(x)); return y;
}
// log2-domain logaddexp: max + lg2(1 + 2^(min-max)). MUFU-only, short chain.
__device__ __forceinline__ float laddexp2(float a, float b) {
    float m = fmaxf(a, b);
    float d = fminf(a, b) - m;
    return m + lg2a(1.0f + ex2a(d));
}
// fast 2^z, FFMA-only (no MUFU). |rel err| ~2e-6.
__device__ __forceinline__ float exp2_fast(float z) {
    float zc = z + 12582912.f;
    int   ni = __float_as_int(zc);
    float n  = zc - 12582912.f;
    float f  = z - n;
    float p  = fmaf(0.0013333558f, f, 0.0096181291f);
    p = fmaf(p, f, 0.0555041087f);
    p = fmaf(p, f, 0.2402265069f);
    p = fmaf(p, f, 0.6931471806f);
    p = fmaf(p, f, 1.0f);
    return __int_as_float(__float_as_int(p) + (ni << 23));
}

// ---------------------------------------------------------------------------
// Kernel 0: convert W fp32 -> fp16
// ---------------------------------------------------------------------------
__global__ void __launch_bounds__(256) convW_kernel(const float* __restrict__ w)
{
    int i = blockIdx.x * 256 + threadIdx.x;          // each handles 8 floats
    const float4* src = reinterpret_cast<const float4*>(w) + (size_t)i * 2;
    float4 v0 = src[0], v1 = src[1];
    __half2 p0 = __floats2half2_rn(v0.x, v0.y);
    __half2 p1 = __floats2half2_rn(v0.z, v0.w);
    __half2 p2 = __floats2half2_rn(v1.x, v1.y);
    __half2 p3 = __floats2half2_rn(v1.z, v1.w);
    uint4 o;
    o.x = *reinterpret_cast<uint32_t*>(&p0);
    o.y = *reinterpret_cast<uint32_t*>(&p1);
    o.z = *reinterpret_cast<uint32_t*>(&p2);
    o.w = *reinterpret_cast<uint32_t*>(&p3);
    *reinterpret_cast<uint4*>(g_Wh + (size_t)i * 8) = o;
}

// ---------------------------------------------------------------------------
// Kernel 0b: build useful-mtile list + balanced per-CTA unit partition.
// Deterministic (function of src_lengths only) -> identical every replay.
// ---------------------------------------------------------------------------
__global__ void schedule_kernel(const int* __restrict__ src)
{
    if (threadIdx.x != 0) return;
    int S[Bn];
#pragma unroll
    for (int b = 0; b < Bn; b++) S[b] = src[b];
    int n = 0;
    for (int mt = 0; mt < MTL; mt++) {
        int b = mt / 33, m = mt % 33;
        if ((m * 128) / 33 < S[b]) g_mtlist[n++] = mt;   // mtile has a row with t < S
    }
    int utot = n * NVT;
    int ub = utot / NCTA, ur = utot % NCTA;
    int acc = 0;
    for (int c = 0; c <= NCTA; c++) {
        g_ustart[c] = acc;
        acc += ub + (c < ur ? 1 : 0);
    }
}

// ---------------------------------------------------------------------------
// Kernel 1: persistent fp16 mma.sync GEMM + fused statistics
//   148 CTAs x 256 threads; length-aware unit partition over (mtile, vtile)
// ---------------------------------------------------------------------------
extern __shared__ char dynsm[];

__device__ __forceinline__ void load_Bchunk(uint32_t Bs, int cg, int stage, int tid)
{
    const __half* wsrc = g_Wh + ((size_t)(cg >> 3)) * 128 * Dn + (cg & 7) * 64;
    const uint32_t dstb = Bs + (uint32_t)stage * 16384u;
#pragma unroll
    for (int it = 0; it < 4; it++) {
        int idx = tid + it * 256;
        int n = idx >> 3, cc = idx & 7;
        cpa16(dstb + n * 128 + ((cc ^ (n & 7))) * 16, wsrc + (size_t)n * Dn + cc * 8);
    }
}

__global__ void __launch_bounds__(256, 1) maingemm_kernel(
    const float* __restrict__ x, const float* __restrict__ bias,
    const int* __restrict__ targets)
{
    const int tid  = threadIdx.x;
    const int lane = tid & 31;
    const int w    = tid >> 5;
    const int wm   = w >> 2;          // 0..1  (64 rows each)
    const int wn   = w & 3;           // 0..3  (32 cols each)
    const int cta  = blockIdx.x;

    const uint32_t sb = smem_u32(dynsm);
    const uint32_t As = sb + SM_A;
    const uint32_t Bs = sb + SM_B;
    float* sbias = (float*)(dynsm + SM_BIAS);
    float* lseb  = (float*)(dynsm + SM_RED);
    float* rawb  = (float*)(dynsm + SM_RED + 2048);

    // ---- bias -> smem once per persistent CTA ----
#pragma unroll
    for (int q = 0; q < 4; q++)
        ((float4*)sbias)[tid + q * 256] = ((const float4*)bias)[tid + q * 256];

    // ---- length-aware work partition (from schedule_kernel) ----
    int u    = g_ustart[cta];
    int uend = g_ustart[cta + 1];

    // ---- per-lane ldmatrix bases (fragment-invariant) ----
    const int arow = wm * 64 + (lane & 15);
    const uint32_t aBase = As + arow * 1024;
    const int alow = lane >> 4;
    const int arx  = arow & 7;
    const int bn   = wn * 32 + ((lane >> 4) << 3) + (lane & 7);
    const int bko  = (lane >> 3) & 1;
    const int bnx  = bn & 7;
    const bool blankown = (wn == 0) && ((lane & 3) == 0);

    uint32_t acc[4][4][2];
#pragma unroll
    for (int a0 = 0; a0 < 4; a0++)
#pragma unroll
        for (int b0 = 0; b0 < 4; b0++) { acc[a0][b0][0] = 0u; acc[a0][b0][1] = 0u; }
    float se[8], sr[8];
#pragma unroll
    for (int i = 0; i < 8; i++) { se[i] = 0.f; sr[i] = 0.f; }

    while (u < uend) {
        const int mt  = g_mtlist[u >> 5];
        const int vt0 = u & 31;
        int nvt = 32 - vt0;
        if (uend - u < nvt) nvt = uend - u;
        const int row0   = mt * 128;
        const int nch    = nvt * 8;
        const int cstart = vt0 * 8;

        // ---- per-fragment row ids + target selectors ----
        int grow[8]; int tkey[8]; int tlo[8];
#pragma unroll
        for (int i = 0; i < 8; i++) {
            int mtl = i >> 1, h = i & 1;
            int gr = row0 + wm * 64 + mtl * 16 + (lane >> 2) + h * 8;
            grow[i] = gr;
            int b = gr / BTU, rem = gr % BTU, uu = rem % U1n;
            int tv = (uu < U1n - 1) ? targets[b * (U1n - 1) + uu] : -1;
            int key = -1, lo = 0;
            if (tv >= 0 && ((tv >> 5) & 3) == wn && (((tv >> 1) & 3) == (lane & 3))) {
                key = tv >> 3;
                lo  = tv & 1;
            }
            tkey[i] = key; tlo[i] = lo;
        }

        // ---- B prologue (stages 0,1) ----
        load_Bchunk(Bs, cstart, 0, tid);
        asm volatile("cp.async.commit_group;" ::: "memory");
        load_Bchunk(Bs, cstart + 1, 1, tid);
        asm volatile("cp.async.commit_group;" ::: "memory");

        // ---- fill A: fp32 -> fp16 into swizzled smem ----
#pragma unroll 4
        for (int it = 0; it < 32; it++) {
            int idx = tid + it * 256;
            int r = idx >> 6, ch = idx & 63;
            const float4* src = reinterpret_cast<const float4*>(
                x + (size_t)(row0 + r) * Dn + ch * 8);
            float4 v0 = src[0], v1 = src[1];
            __half2 p0 = __floats2half2_rn(v0.x, v0.y);
            __half2 p1 = __floats2half2_rn(v0.z, v0.w);
            __half2 p2 = __floats2half2_rn(v1.x, v1.y);
            __half2 p3 = __floats2half2_rn(v1.z, v1.w);
            uint32_t dchunk = (uint32_t)((ch & ~7) | ((ch ^ r) & 7));
            uint32_t dst = As + r * 1024 + dchunk * 16;
            asm volatile("st.shared.v4.b32 [%0], {%1,%2,%3,%4};" ::
                "r"(dst),
                "r"(*reinterpret_cast<uint32_t*>(&p0)), "r"(*reinterpret_cast<uint32_t*>(&p1)),
                "r"(*reinterpret_cast<uint32_t*>(&p2)), "r"(*reinterpret_cast<uint32_t*>(&p3))
                : "memory");
        }

        for (int ct = 0; ct < nch; ct++) {
            const int cg = cstart + ct;
            const int vt = cg >> 3, kc = cg & 7, st = ct % 3;
            __syncthreads();                       // stage (ct+2)%3 free / A-fill barrier
            if (ct + 2 < nch) {
                load_Bchunk(Bs, cstart + ct + 2, (ct + 2) % 3, tid);
                asm volatile("cp.async.commit_group;" ::: "memory");
                asm volatile("cp.async.wait_group 2;" ::: "memory");
            } else if (ct + 1 < nch) {
                asm volatile("cp.async.wait_group 1;" ::: "memory");
            } else {
                asm volatile("cp.async.wait_group 0;" ::: "memory");
            }
            __syncthreads();                       // chunk ct visible

            const uint32_t aCh = aBase + kc * 128;
            const uint32_t bSt = Bs + (uint32_t)st * 16384u + bn * 128;
#pragma unroll
            for (int ks = 0; ks < 4; ks++) {
                uint32_t afr[4][4];
#pragma unroll
                for (int mtl = 0; mtl < 4; mtl++) {
                    uint32_t ad = aCh + mtl * 16384 + (uint32_t)(((ks * 2 + alow) ^ arx)) * 16;
                    asm volatile("ldmatrix.sync.aligned.m8n8.x4.shared.b16 {%0,%1,%2,%3}, [%4];"
                        : "=r"(afr[mtl][0]), "=r"(afr[mtl][1]), "=r"(afr[mtl][2]), "=r"(afr[mtl][3])
                        : "r"(ad));
                }
                uint32_t bfr[2][4];
#pragma unroll
                for (int np = 0; np < 2; np++) {
                    uint32_t bd = bSt + np * 2048 + (uint32_t)(((ks * 2 + bko) ^ bnx)) * 16;
                    asm volatile("ldmatrix.sync.aligned.m8n8.x4.shared.b16 {%0,%1,%2,%3}, [%4];"
                        : "=r"(bfr[np][0]), "=r"(bfr[np][1]), "=r"(bfr[np][2]), "=r"(bfr[np][3])
                        : "r"(bd));
                }
#pragma unroll
                for (int mtl = 0; mtl < 4; mtl++)
#pragma unroll
                    for (int nt = 0; nt < 4; nt++) {
                        asm volatile("mma.sync.aligned.m16n8k16.row.col.f16.f16.f16.f16 "
                            "{%0,%1}, {%2,%3,%4,%5}, {%6,%7}, {%0,%1};"
                            : "+r"(acc[mtl][nt][0]), "+r"(acc[mtl][nt][1])
                            : "r"(afr[mtl][0]), "r"(afr[mtl][1]), "r"(afr[mtl][2]), "r"(afr[mtl][3]),
                              "r"(bfr[nt >> 1][(nt & 1) * 2]), "r"(bfr[nt >> 1][(nt & 1) * 2 + 1]));
                    }
            }

            if (kc == 7) {
                // ---- register-only epilogue for vtile vt ----
                float bcol[8];
#pragma unroll
                for (int nt = 0; nt < 4; nt++) {
                    bcol[nt * 2]     = sbias[vt * 128 + wn * 32 + nt * 8 + (lane & 3) * 2];
                    bcol[nt * 2 + 1] = sbias[vt * 128 + wn * 32 + nt * 8 + (lane & 3) * 2 + 1];
                }
                const int vbase = vt * 16 + wn * 4;
#pragma unroll
                for (int mtl = 0; mtl < 4; mtl++)
#pragma unroll
                    for (int h = 0; h < 2; h++) {
                        const int i = mtl * 2 + h;
#pragma unroll
                        for (int nt = 0; nt < 4; nt++) {
                            uint32_t pk = acc[mtl][nt][h];
                            float2 fv = __half22float2(*reinterpret_cast<__half2*>(&pk));
#pragma unroll
                            for (int lo = 0; lo < 2; lo++) {
                                float y = (lo ? fv.y : fv.x) + bcol[nt * 2 + lo];
                                sr[i] += y;
                                se[i] += exp2_fast(y * L2E);
                                if (tkey[i] == vbase + nt && tlo[i] == lo)
                                    g_tgt[grow[i]] = y;
                                if (vt == 0 && nt == 0 && lo == 0 && blankown)
                                    g_blank[grow[i]] = y;
                            }
                        }
                    }
#pragma unroll
                for (int a0 = 0; a0 < 4; a0++)
#pragma unroll
                    for (int b0 = 0; b0 < 4; b0++) { acc[a0][b0][0] = 0u; acc[a0][b0][1] = 0u; }
            }
        }

        // ---- fragment partial reduction + slotted write ----
#pragma unroll
        for (int i = 0; i < 8; i++) {
            se[i] += __shfl_xor_sync(0xffffffffu, se[i], 1);
            se[i] += __shfl_xor_sync(0xffffffffu, se[i], 2);
            sr[i] += __shfl_xor_sync(0xffffffffu, sr[i], 1);
            sr[i] += __shfl_xor_sync(0xffffffffu, sr[i], 2);
        }
        __syncthreads();
        if ((lane & 3) == 0) {
#pragma unroll
            for (int i = 0; i < 8; i++) {
                int mtl = i >> 1, h = i & 1;
                int lr = wm * 64 + mtl * 16 + (lane >> 2) + h * 8;
                lseb[wn * 128 + lr] = se[i];
                rawb[wn * 128 + lr] = sr[i];
            }
        }
        __syncthreads();
        if (tid < 128) {
            float E = (lseb[tid] + lseb[128 + tid]) + (lseb[256 + tid] + lseb[384 + tid]);
            float R = (rawb[tid] + rawb[128 + tid]) + (rawb[256 + tid] + rawb[384 + tid]);
            // segment -> slot: start / end / middle (3-way splits possible)
            if (vt0 == 0)             { g_pE0[row0 + tid] = E; g_pR0[row0 + tid] = R; }
            else if (vt0 + nvt == 32) { g_pE1[row0 + tid] = E; g_pR1[row0 + tid] = R; }
            else                      { g_pE2[row0 + tid] = E; g_pR2[row0 + tid] = R; }
        }
#pragma unroll
        for (int i = 0; i < 8; i++) { se[i] = 0.f; sr[i] = 0.f; }

        u += nvt;
    }
}

// ---------------------------------------------------------------------------
// Kernel 2: per-batch DP in log2 domain (padded, conflict-free smem; MUFU
// laddexp) + label-smoothed CE + final sum
// ---------------------------------------------------------------------------
__global__ void __launch_bounds__(256) finalize_kernel(
    const int* __restrict__ targets,
    const int* __restrict__ src_lengths,
    const int* __restrict__ tgt_lengths,
    float* __restrict__ out)
{
    __shared__ float sbl[BTUP];
    __shared__ float sem[BTUP];
    __shared__ float s_dp;
    const int b = blockIdx.x;
    const int tid = threadIdx.x;
    const int base = b * BTU;

    // stage lattice in log2 domain, stride-34 padded (bank-conflict-free DP)
    for (int i = tid; i < BTU; i += 256) {
        int t = i / U1n, uu = i - t * U1n;
        float E = (g_pE0[base + i] + g_pE1[base + i]) + g_pE2[base + i];
        float l2 = lg2a(E);
        int p = t * U1P + uu;
        sbl[p] = fmaf(g_blank[base + i], L2E, -l2);
        sem[p] = fmaf(g_tgt[base + i],  L2E, -l2);
    }
    __syncthreads();

    if (tid < 32) {
        const int lane = tid;
        const int S  = src_lengths[b];
        const int TG = tgt_lengths[b];
        float cur = 0.f, cur2 = 0.f, afin = 0.f;
        bool have = false;
        const int nsteps = (S - 1) + 32;
        for (int s = 0; s <= nsteps; s++) {
            float left   = __shfl_up_sync(0xffffffffu, cur, 1);
            float prev31 = cur;
            int t = s - lane;
            if (t >= 0 && t <= S - 1) {
                int uu = lane;
                if (t == 0) {
                    cur = (uu == 0) ? 0.f : left + sem[uu - 1];
                } else {
                    float up = cur + sbl[(t - 1) * U1P + uu];
                    cur = (uu == 0) ? up : laddexp2(up, left + sem[t * U1P + (uu - 1)]);
                }
                if (t == S - 1 && uu == TG) { afin = cur; have = true; }
            }
            if (lane == 31) {
                int t2 = s - 32;
                if (t2 >= 0 && t2 <= S - 1) {
                    float lft = prev31 + sem[t2 * U1P + 31];
                    cur2 = (t2 == 0) ? lft : laddexp2(cur2 + sbl[(t2 - 1) * U1P + 32], lft);
                    if (t2 == S - 1 && TG == 32) { afin = cur2; have = true; }
                }
            }
        }
        float lossb = have ? -(afin + sbl[(S - 1) * U1P + TG]) * LN2 : 0.f;
#pragma unroll
        for (int o = 16; o > 0; o >>= 1)
            lossb += __shfl_xor_sync(0xffffffffu, lossb, o);
        if (lane == 0) s_dp = lossb;
    }
    __syncthreads();

    if (tid < 32) {
        const int uu = tid;
        const int S = src_lengths[b];
        const int tv = targets[b * (U1n - 1) + uu];
        const int row = b * BTU + (S - 1) * U1n + uu;
        float E = (g_pE0[row] + g_pE1[row]) + g_pE2[row];
        float lse = lg2a(E) * LN2;
        float R = (g_pR0[row] + g_pR1[row]) + g_pR2[row];
        float nll = lse - g_tgt[row];
        float smooth = (float)Vn * lse - R;
        const float LS = 0.1f;
        const float eps = LS / (float)(Vn - 1);
        float m = (tv != 1) ? 1.f : 0.f;
        float term = ((1.f - LS - eps) * nll + eps * smooth) * m;
#pragma unroll
        for (int o = 16; o > 0; o >>= 1)
            term += __shfl_xor_sync(0xffffffffu, term, o);
        if (uu == 0) {
            g_part[b] = s_dp + term;
            __threadfence();
            unsigned t = atomicAdd(&g_done, 1u);
            if (t == (unsigned)(Bn - 1)) {
                __threadfence();
                float s = 0.f;
#pragma unroll
                for (int bb = 0; bb < Bn; bb++) s += g_part[bb];
                out[0] = s;
                g_done = 0u;           // reset for next graph replay
            }
        }
    }
}

// ---------------------------------------------------------------------------
extern "C" void kernel_launch(void* const* d_in, const int* in_sizes, int n_in,
                              void* d_out, int out_size)
{
    const float* x       = (const float*)d_in[0];
    const float* wgt     = (const float*)d_in[1];
    const float* bias    = (const float*)d_in[2];
    const int*   targets = (const int*)d_in[3];
    const int*   src     = (const int*)d_in[4];
    const int*   tgt     = (const int*)d_in[5];
    float* out = (float*)d_out;

    static bool attr_set = false;
    if (!attr_set) {
        cudaFuncSetAttribute(maingemm_kernel,
                             cudaFuncAttributeMaxDynamicSharedMemorySize, SM_TOT);
        attr_set = true;
    }

    convW_kernel<<<(Vn * Dn / 8) / 256, 256>>>(wgt);
    schedule_kernel<<<1, 32>>>(src);
    maingemm_kernel<<<NCTA, 256, SM_TOT>>>(x, bias, targets);
    finalize_kernel<<<Bn, 256>>>(targets, src, tgt, out);
}

// round 14
// speedup vs baseline: 2.5292x; 1.0726x over previous
#include <cuda_runtime.h>
#include <cuda_fp16.h>
#include <math.h>
#include <stdint.h>

#define Bn   8
#define Tn   128
#define U1n  33
#define Dn   512
#define Vn   4096
#define BTU  (Tn*U1n)          // 4224
#define ROWS (Bn*BTU)          // 33792
#define MTL  (ROWS/128)        // 264 M-tiles (33 per batch)
#define NVT  (Vn/128)          // 32 vocab tiles
#define NCTA 148
#define L2E  1.442695040888963f
#define LN2  0.6931471805599453f
#define U1P  34                // padded lattice stride (bank-conflict-free)
#define BTUP (Tn*U1P)          // 4352

// smem layout (bytes) for maingemm
#define SM_A     0u            // 128 x 512 fp16 = 131072
#define SM_B     131072u       // 3 stages x 16384 (128n x 64k fp16)
#define SM_BIAS  180224u       // 4096 floats = 16384
#define SM_RED   196608u       // 2 x 512 floats = 4096
#define SM_TOT   200704u

// ---------------- device scratch ----------------
__device__ __align__(16) __half g_Wh[(size_t)Vn*Dn];
__device__ float g_pE0[ROWS];   // start segments (vt0 == 0)
__device__ float g_pE1[ROWS];   // end segments (vt0 > 0, reaches vtile 31)
__device__ float g_pE2[ROWS];   // middle segments (rare 3-way splits)
__device__ float g_pR0[ROWS];
__device__ float g_pR1[ROWS];
__device__ float g_pR2[ROWS];
__device__ float g_blank[ROWS];
__device__ float g_tgt[ROWS];
__device__ float g_part[Bn];
__device__ unsigned g_done;
__device__ int g_mtlist[MTL];          // useful mtile ids
__device__ int g_ustart[NCTA + 1];     // per-CTA unit ranges

// ---------------- helpers ----------------
__device__ __forceinline__ uint32_t smem_u32(const void* p) {
    uint32_t a;
    asm("{ .reg .u64 t; cvta.to.shared.u64 t, %1; cvt.u32.u64 %0, t; }" : "=r"(a) : "l"(p));
    return a;
}
__device__ __forceinline__ void cpa16(uint32_t dst, const void* src) {
    asm volatile("cp.async.cg.shared.global [%0], [%1], 16;" :: "r"(dst), "l"(src));
}
__device__ __forceinline__ float ex2a(float x) {
    float y; asm("ex2.approx.ftz.f32 %0, %1;" : "=f"(y) : "f"(x)); return y;
}
__device__ __forceinline__ float lg2a(float x) {
    float y; asm("lg2.approx.ftz.f32 %0, %1;" : "=f"(y) : "f"(x)); return y;
}
// log2-domain logaddexp: max + lg2(1 + 2^(min-max)). MUFU-only, short chain.
__device__ __forceinline__ float laddexp2(float a, float b) {
    float m = fmaxf(a, b);
    float d = fminf(a, b) - m;
    return m + lg2a(1.0f + ex2a(d));
}
// fast 2^z, FFMA-only (no MUFU). |rel err| ~2e-6.
__device__ __forceinline__ float exp2_fast(float z) {
    float zc = z + 12582912.f;
    int   ni = __float_as_int(zc);
    float n  = zc - 12582912.f;
    float f  = z - n;
    float p  = fmaf(0.0013333558f, f, 0.0096181291f);
    p = fmaf(p, f, 0.0555041087f);
    p = fmaf(p, f, 0.2402265069f);
    p = fmaf(p, f, 0.6931471806f);
    p = fmaf(p, f, 1.0f);
    return __int_as_float(__float_as_int(p) + (ni << 23));
}

// ---------------------------------------------------------------------------
// Kernel 0: convert W fp32 -> fp16
// ---------------------------------------------------------------------------
__global__ void __launch_bounds__(256) convW_kernel(const float* __restrict__ w)
{
    int i = blockIdx.x * 256 + threadIdx.x;          // each handles 8 floats
    const float4* src = reinterpret_cast<const float4*>(w) + (size_t)i * 2;
    float4 v0 = src[0], v1 = src[1];
    __half2 p0 = __floats2half2_rn(v0.x, v0.y);
    __half2 p1 = __floats2half2_rn(v0.z, v0.w);
    __half2 p2 = __floats2half2_rn(v1.x, v1.y);
    __half2 p3 = __floats2half2_rn(v1.z, v1.w);
    uint4 o;
    o.x = *reinterpret_cast<uint32_t*>(&p0);
    o.y = *reinterpret_cast<uint32_t*>(&p1);
    o.z = *reinterpret_cast<uint32_t*>(&p2);
    o.w = *reinterpret_cast<uint32_t*>(&p3);
    *reinterpret_cast<uint4*>(g_Wh + (size_t)i * 8) = o;
}

// ---------------------------------------------------------------------------
// Kernel 0b: build useful-mtile list + balanced per-CTA unit partition.
// Deterministic (function of src_lengths only) -> identical every replay.
// ---------------------------------------------------------------------------
__global__ void schedule_kernel(const int* __restrict__ src)
{
    if (threadIdx.x != 0) return;
    int S[Bn];
#pragma unroll
    for (int b = 0; b < Bn; b++) S[b] = src[b];
    int n = 0;
    for (int mt = 0; mt < MTL; mt++) {
        int b = mt / 33, m = mt % 33;
        if ((m * 128) / 33 < S[b]) g_mtlist[n++] = mt;   // mtile has a row with t < S
    }
    int utot = n * NVT;
    int ub = utot / NCTA, ur = utot % NCTA;
    int acc = 0;
    for (int c = 0; c <= NCTA; c++) {
        g_ustart[c] = acc;
        acc += ub + (c < ur ? 1 : 0);
    }
}

// ---------------------------------------------------------------------------
// Kernel 1: persistent fp16 mma.sync GEMM + fused statistics
//   148 CTAs x 256 threads; length-aware unit partition over (mtile, vtile)
// ---------------------------------------------------------------------------
extern __shared__ char dynsm[];

__device__ __forceinline__ void load_Bchunk(uint32_t Bs, int cg, int stage, int tid)
{
    const __half* wsrc = g_Wh + ((size_t)(cg >> 3)) * 128 * Dn + (cg & 7) * 64;
    const uint32_t dstb = Bs + (uint32_t)stage * 16384u;
#pragma unroll
    for (int it = 0; it < 4; it++) {
        int idx = tid + it * 256;
        int n = idx >> 3, cc = idx & 7;
        cpa16(dstb + n * 128 + ((cc ^ (n & 7))) * 16, wsrc + (size_t)n * Dn + cc * 8);
    }
}

__global__ void __launch_bounds__(256, 1) maingemm_kernel(
    const float* __restrict__ x, const float* __restrict__ bias,
    const int* __restrict__ targets)
{
    const int tid  = threadIdx.x;
    const int lane = tid & 31;
    const int w    = tid >> 5;
    const int wm   = w >> 2;          // 0..1  (64 rows each)
    const int wn   = w & 3;           // 0..3  (32 cols each)
    const int cta  = blockIdx.x;

    const uint32_t sb = smem_u32(dynsm);
    const uint32_t As = sb + SM_A;
    const uint32_t Bs = sb + SM_B;
    float* sbias = (float*)(dynsm + SM_BIAS);
    float* lseb  = (float*)(dynsm + SM_RED);
    float* rawb  = (float*)(dynsm + SM_RED + 2048);

    // ---- bias -> smem once per persistent CTA ----
#pragma unroll
    for (int q = 0; q < 4; q++)
        ((float4*)sbias)[tid + q * 256] = ((const float4*)bias)[tid + q * 256];

    // ---- length-aware work partition (from schedule_kernel) ----
    int u    = g_ustart[cta];
    int uend = g_ustart[cta + 1];

    // ---- per-lane ldmatrix bases (fragment-invariant) ----
    const int arow = wm * 64 + (lane & 15);
    const uint32_t aBase = As + arow * 1024;
    const int alow = lane >> 4;
    const int arx  = arow & 7;
    const int bn   = wn * 32 + ((lane >> 4) << 3) + (lane & 7);
    const int bko  = (lane >> 3) & 1;
    const int bnx  = bn & 7;
    const bool blankown = (wn == 0) && ((lane & 3) == 0);

    uint32_t acc[4][4][2];
#pragma unroll
    for (int a0 = 0; a0 < 4; a0++)
#pragma unroll
        for (int b0 = 0; b0 < 4; b0++) { acc[a0][b0][0] = 0u; acc[a0][b0][1] = 0u; }
    float se[8], sr[8];
#pragma unroll
    for (int i = 0; i < 8; i++) { se[i] = 0.f; sr[i] = 0.f; }

    while (u < uend) {
        const int mt  = g_mtlist[u >> 5];
        const int vt0 = u & 31;
        int nvt = 32 - vt0;
        if (uend - u < nvt) nvt = uend - u;
        const int row0   = mt * 128;
        const int nch    = nvt * 8;
        const int cstart = vt0 * 8;

        // ---- per-fragment row ids + target selectors ----
        int grow[8]; int tkey[8]; int tlo[8];
#pragma unroll
        for (int i = 0; i < 8; i++) {
            int mtl = i >> 1, h = i & 1;
            int gr = row0 + wm * 64 + mtl * 16 + (lane >> 2) + h * 8;
            grow[i] = gr;
            int b = gr / BTU, rem = gr % BTU, uu = rem % U1n;
            int tv = (uu < U1n - 1) ? targets[b * (U1n - 1) + uu] : -1;
            int key = -1, lo = 0;
            if (tv >= 0 && ((tv >> 5) & 3) == wn && (((tv >> 1) & 3) == (lane & 3))) {
                key = tv >> 3;
                lo  = tv & 1;
            }
            tkey[i] = key; tlo[i] = lo;
        }

        // ---- B prologue (stages 0,1) ----
        load_Bchunk(Bs, cstart, 0, tid);
        asm volatile("cp.async.commit_group;" ::: "memory");
        load_Bchunk(Bs, cstart + 1, 1, tid);
        asm volatile("cp.async.commit_group;" ::: "memory");

        // ---- fill A: fp32 -> fp16 into swizzled smem ----
#pragma unroll 4
        for (int it = 0; it < 32; it++) {
            int idx = tid + it * 256;
            int r = idx >> 6, ch = idx & 63;
            const float4* src = reinterpret_cast<const float4*>(
                x + (size_t)(row0 + r) * Dn + ch * 8);
            float4 v0 = src[0], v1 = src[1];
            __half2 p0 = __floats2half2_rn(v0.x, v0.y);
            __half2 p1 = __floats2half2_rn(v0.z, v0.w);
            __half2 p2 = __floats2half2_rn(v1.x, v1.y);
            __half2 p3 = __floats2half2_rn(v1.z, v1.w);
            uint32_t dchunk = (uint32_t)((ch & ~7) | ((ch ^ r) & 7));
            uint32_t dst = As + r * 1024 + dchunk * 16;
            asm volatile("st.shared.v4.b32 [%0], {%1,%2,%3,%4};" ::
                "r"(dst),
                "r"(*reinterpret_cast<uint32_t*>(&p0)), "r"(*reinterpret_cast<uint32_t*>(&p1)),
                "r"(*reinterpret_cast<uint32_t*>(&p2)), "r"(*reinterpret_cast<uint32_t*>(&p3))
                : "memory");
        }

        for (int ct = 0; ct < nch; ct++) {
            const int cg = cstart + ct;
            const int vt = cg >> 3, kc = cg & 7, st = ct % 3;
            __syncthreads();                       // stage (ct+2)%3 free / A-fill barrier
            if (ct + 2 < nch) {
                load_Bchunk(Bs, cstart + ct + 2, (ct + 2) % 3, tid);
                asm volatile("cp.async.commit_group;" ::: "memory");
                asm volatile("cp.async.wait_group 2;" ::: "memory");
            } else if (ct + 1 < nch) {
                asm volatile("cp.async.wait_group 1;" ::: "memory");
            } else {
                asm volatile("cp.async.wait_group 0;" ::: "memory");
            }
            __syncthreads();                       // chunk ct visible

            const uint32_t aCh = aBase + kc * 128;
            const uint32_t bSt = Bs + (uint32_t)st * 16384u + bn * 128;
#pragma unroll
            for (int ks = 0; ks < 4; ks++) {
                uint32_t afr[4][4];
#pragma unroll
                for (int mtl = 0; mtl < 4; mtl++) {
                    uint32_t ad = aCh + mtl * 16384 + (uint32_t)(((ks * 2 + alow) ^ arx)) * 16;
                    asm volatile("ldmatrix.sync.aligned.m8n8.x4.shared.b16 {%0,%1,%2,%3}, [%4];"
                        : "=r"(afr[mtl][0]), "=r"(afr[mtl][1]), "=r"(afr[mtl][2]), "=r"(afr[mtl][3])
                        : "r"(ad));
                }
                uint32_t bfr[2][4];
#pragma unroll
                for (int np = 0; np < 2; np++) {
                    uint32_t bd = bSt + np * 2048 + (uint32_t)(((ks * 2 + bko) ^ bnx)) * 16;
                    asm volatile("ldmatrix.sync.aligned.m8n8.x4.shared.b16 {%0,%1,%2,%3}, [%4];"
                        : "=r"(bfr[np][0]), "=r"(bfr[np][1]), "=r"(bfr[np][2]), "=r"(bfr[np][3])
                        : "r"(bd));
                }
#pragma unroll
                for (int mtl = 0; mtl < 4; mtl++)
#pragma unroll
                    for (int nt = 0; nt < 4; nt++) {
                        asm volatile("mma.sync.aligned.m16n8k16.row.col.f16.f16.f16.f16 "
                            "{%0,%1}, {%2,%3,%4,%5}, {%6,%7}, {%0,%1};"
                            : "+r"(acc[mtl][nt][0]), "+r"(acc[mtl][nt][1])
                            : "r"(afr[mtl][0]), "r"(afr[mtl][1]), "r"(afr[mtl][2]), "r"(afr[mtl][3]),
                              "r"(bfr[nt >> 1][(nt & 1) * 2]), "r"(bfr[nt >> 1][(nt & 1) * 2 + 1]));
                    }
            }

            if (kc == 7) {
                // ---- register-only epilogue for vtile vt ----
                float bcol[8];
#pragma unroll
                for (int nt = 0; nt < 4; nt++) {
                    bcol[nt * 2]     = sbias[vt * 128 + wn * 32 + nt * 8 + (lane & 3) * 2];
                    bcol[nt * 2 + 1] = sbias[vt * 128 + wn * 32 + nt * 8 + (lane & 3) * 2 + 1];
                }
                const int vbase = vt * 16 + wn * 4;
#pragma unroll
                for (int mtl = 0; mtl < 4; mtl++)
#pragma unroll
                    for (int h = 0; h < 2; h++) {
                        const int i = mtl * 2 + h;
#pragma unroll
                        for (int nt = 0; nt < 4; nt++) {
                            uint32_t pk = acc[mtl][nt][h];
                            float2 fv = __half22float2(*reinterpret_cast<__half2*>(&pk));
#pragma unroll
                            for (int lo = 0; lo < 2; lo++) {
                                float y = (lo ? fv.y : fv.x) + bcol[nt * 2 + lo];
                                sr[i] += y;
                                se[i] += exp2_fast(y * L2E);
                                if (tkey[i] == vbase + nt && tlo[i] == lo)
                                    g_tgt[grow[i]] = y;
                                if (vt == 0 && nt == 0 && lo == 0 && blankown)
                                    g_blank[grow[i]] = y;
                            }
                        }
                    }
#pragma unroll
                for (int a0 = 0; a0 < 4; a0++)
#pragma unroll
                    for (int b0 = 0; b0 < 4; b0++) { acc[a0][b0][0] = 0u; acc[a0][b0][1] = 0u; }
            }
        }

        // ---- fragment partial reduction + slotted write ----
#pragma unroll
        for (int i = 0; i < 8; i++) {
            se[i] += __shfl_xor_sync(0xffffffffu, se[i], 1);
            se[i] += __shfl_xor_sync(0xffffffffu, se[i], 2);
            sr[i] += __shfl_xor_sync(0xffffffffu, sr[i], 1);
            sr[i] += __shfl_xor_sync(0xffffffffu, sr[i], 2);
        }
        __syncthreads();
        if ((lane & 3) == 0) {
#pragma unroll
            for (int i = 0; i < 8; i++) {
                int mtl = i >> 1, h = i & 1;
                int lr = wm * 64 + mtl * 16 + (lane >> 2) + h * 8;
                lseb[wn * 128 + lr] = se[i];
                rawb[wn * 128 + lr] = sr[i];
            }
        }
        __syncthreads();
        if (tid < 128) {
            float E = (lseb[tid] + lseb[128 + tid]) + (lseb[256 + tid] + lseb[384 + tid]);
            float R = (rawb[tid] + rawb[128 + tid]) + (rawb[256 + tid] + rawb[384 + tid]);
            // segment -> slot: start / end / middle (3-way splits possible)
            if (vt0 == 0)             { g_pE0[row0 + tid] = E; g_pR0[row0 + tid] = R; }
            else if (vt0 + nvt == 32) { g_pE1[row0 + tid] = E; g_pR1[row0 + tid] = R; }
            else                      { g_pE2[row0 + tid] = E; g_pR2[row0 + tid] = R; }
        }
#pragma unroll
        for (int i = 0; i < 8; i++) { se[i] = 0.f; sr[i] = 0.f; }

        u += nvt;
    }
}

// ---------------------------------------------------------------------------
// Kernel 2: per-batch DP, branch-free (predicated selects, clamped indices),
// log2 domain + label-smoothed CE + final sum
// ---------------------------------------------------------------------------
__global__ void __launch_bounds__(256) finalize_kernel(
    const int* __restrict__ targets,
    const int* __restrict__ src_lengths,
    const int* __restrict__ tgt_lengths,
    float* __restrict__ out)
{
    __shared__ float sbl[BTUP];
    __shared__ float sem[BTUP];
    __shared__ float s_dp;
    const int b = blockIdx.x;
    const int tid = threadIdx.x;
    const int base = b * BTU;

    // stage lattice in log2 domain, stride-34 padded (bank-conflict-free DP)
    for (int i = tid; i < BTU; i += 256) {
        int t = i / U1n, uu = i - t * U1n;
        float E = (g_pE0[base + i] + g_pE1[base + i]) + g_pE2[base + i];
        float l2 = lg2a(E);
        int p = t * U1P + uu;
        sbl[p] = fmaf(g_blank[base + i], L2E, -l2);
        sem[p] = fmaf(g_tgt[base + i],  L2E, -l2);
    }
    __syncthreads();

    if (tid < 32) {
        const int lane = tid;
        const int S  = src_lengths[b];
        const int TG = tgt_lengths[b];

        // ---- alpha0 via Kogge-Stone exclusive scan of sem[0..30] ----
        float v = sem[(lane == 0) ? 0 : (lane - 1)];
        v = (lane == 0) ? 0.f : v;
#pragma unroll
        for (int o = 1; o < 32; o <<= 1) {
            float nv = __shfl_up_sync(0xffffffffu, v, o);
            v += (lane >= o) ? nv : 0.f;
        }
        float cur  = v;                                        // alpha[0][lane]
        float cur2 = __shfl_sync(0xffffffffu, cur, 31) + sem[31];  // alpha[0][32]

        float afin = 0.f, haveF = 0.f;
        const int nsteps = (S - 1) + 32;
        for (int s = 1; s <= nsteps; s++) {
            float left   = __shfl_up_sync(0xffffffffu, cur, 1);
            float prev31 = cur;                                // lane31: alpha[t2][31]
            int t  = s - lane;
            int tc = max(1, min(t, S - 1));
            float up   = cur + sbl[(tc - 1) * U1P + lane];
            float alt  = left + sem[tc * U1P + ((lane == 0) ? 0 : (lane - 1))];
            float cand = laddexp2(up, alt);
            cand = (lane == 0) ? up : cand;
            bool valid = (t >= 1) && (t <= S - 1);
            cur = valid ? cand : cur;
            bool hit = valid && (t == S - 1) && (lane == TG);
            afin  = hit ? cur : afin;
            haveF = hit ? 1.f : haveF;
            // column u=32: computed by all lanes; only lane31's value is real
            int t2  = s - 32;
            int t2c = max(1, min(t2, S - 1));
            float up2   = cur2 + sbl[(t2c - 1) * U1P + 32];
            float alt2  = prev31 + sem[t2c * U1P + 31];
            float cand2 = laddexp2(up2, alt2);
            bool valid2 = (t2 >= 1) && (t2 <= S - 1);
            cur2 = valid2 ? cand2 : cur2;
            bool hit2 = valid2 && (t2 == S - 1) && (TG == 32) && (lane == 31);
            afin  = hit2 ? cur2 : afin;
            haveF = hit2 ? 1.f : haveF;
        }
        float lossb = -(afin + sbl[(S - 1) * U1P + TG]) * LN2 * haveF;
#pragma unroll
        for (int o = 16; o > 0; o >>= 1)
            lossb += __shfl_xor_sync(0xffffffffu, lossb, o);
        if (lane == 0) s_dp = lossb;
    }
    __syncthreads();

    if (tid < 32) {
        const int uu = tid;
        const int S = src_lengths[b];
        const int tv = targets[b * (U1n - 1) + uu];
        const int row = b * BTU + (S - 1) * U1n + uu;
        float E = (g_pE0[row] + g_pE1[row]) + g_pE2[row];
        float lse = lg2a(E) * LN2;
        float R = (g_pR0[row] + g_pR1[row]) + g_pR2[row];
        float nll = lse - g_tgt[row];
        float smooth = (float)Vn * lse - R;
        const float LS = 0.1f;
        const float eps = LS / (float)(Vn - 1);
        float m = (tv != 1) ? 1.f : 0.f;
        float term = ((1.f - LS - eps) * nll + eps * smooth) * m;
#pragma unroll
        for (int o = 16; o > 0; o >>= 1)
            term += __shfl_xor_sync(0xffffffffu, term, o);
        if (uu == 0) {
            g_part[b] = s_dp + term;
            __threadfence();
            unsigned t = atomicAdd(&g_done, 1u);
            if (t == (unsigned)(Bn - 1)) {
                __threadfence();
                float s = 0.f;
#pragma unroll
                for (int bb = 0; bb < Bn; bb++) s += g_part[bb];
                out[0] = s;
                g_done = 0u;           // reset for next graph replay
            }
        }
    }
}

// ---------------------------------------------------------------------------
extern "C" void kernel_launch(void* const* d_in, const int* in_sizes, int n_in,
                              void* d_out, int out_size)
{
    const float* x       = (const float*)d_in[0];
    const float* wgt     = (const float*)d_in[1];
    const float* bias    = (const float*)d_in[2];
    const int*   targets = (const int*)d_in[3];
    const int*   src     = (const int*)d_in[4];
    const int*   tgt     = (const int*)d_in[5];
    float* out = (float*)d_out;

    static bool attr_set = false;
    if (!attr_set) {
        cudaFuncSetAttribute(maingemm_kernel,
                             cudaFuncAttributeMaxDynamicSharedMemorySize, SM_TOT);
        attr_set = true;
    }

    convW_kernel<<<(Vn * Dn / 8) / 256, 256>>>(wgt);
    schedule_kernel<<<1, 32>>>(src);
    maingemm_kernel<<<NCTA, 256, SM_TOT>>>(x, bias, targets);
    finalize_kernel<<<Bn, 256>>>(targets, src, tgt, out);
}